// round 15
// baseline (speedup 1.0000x reference)
#include <cuda_runtime.h>
#include <cuda_fp16.h>
#include <math.h>
#include <stdint.h>

#define NTOK 2048
#define DDIM 1024
#define NEXP 8
#define FDIM 2048
#define NASS (NTOK * 2)

// GEMM tiling: CTA 128x256, warp 64x64 (8 warps = 256 threads), BK=32
#define BM 128
#define BN 256
#define BK 32
#define THREADS 256

// fp16 fragment-major smem (double-buffered), m16n8k16 => 2 ks-slices per BK=32
//  A: 16 groups (MI 0..7 x ks 0..1), each 33 lines x 16B (line = lane's 4-reg frag)
//  B: 64 groups (NI 0..31 x ks 0..1), each 33 lines x 8B
#define A_GRP_BYTES (33 * 16)
#define B_GRP_BYTES (33 * 8)
#define A_BUF_BYTES (16 * A_GRP_BYTES)      // 8448
#define B_BUF_BYTES (64 * B_GRP_BYTES)      // 16896
#define STAGE_BYTES (A_BUF_BYTES + B_BUF_BYTES)   // 25344
#define SM_META     (2 * STAGE_BYTES)             // 50688
#define SM_TOTAL    (SM_META + 512 * 3)           // 52224

// ---------------- scratch (device globals) ---------------------------------
__device__ int   g_cnt[NEXP];
__device__ int   g_rows[NEXP][NTOK];
__device__ float g_gate[NASS];
__device__ float g_act[(size_t)NASS * FDIM];   // 32 MB
__device__ float g_y[(size_t)NASS * DDIM];     // 16 MB

// ---------------- helpers ---------------------------------------------------
__device__ __forceinline__ uint32_t f2h2(float a, float b) {   // packed rn half2
    __half2 h = __floats2half2_rn(a, b);
    return *(uint32_t*)&h;
}
__device__ __forceinline__ void mma_f16(float* c, const unsigned* a, const unsigned* b) {
    asm volatile(
        "mma.sync.aligned.m16n8k16.row.col.f32.f16.f16.f32 "
        "{%0,%1,%2,%3}, {%4,%5,%6,%7}, {%8,%9}, {%0,%1,%2,%3};"
        : "+f"(c[0]), "+f"(c[1]), "+f"(c[2]), "+f"(c[3])
        : "r"(a[0]), "r"(a[1]), "r"(a[2]), "r"(a[3]), "r"(b[0]), "r"(b[1]));
}

// ---------------- kernel 0: zero expert counters ---------------------------
__global__ void k_zero() {
    if (threadIdx.x < NEXP) g_cnt[threadIdx.x] = 0;
}

// ---------------- kernel 1: router (one warp per token) --------------------
__global__ void k_router(const float* __restrict__ x, const float* __restrict__ Wr) {
    int warp = (blockIdx.x * blockDim.x + threadIdx.x) >> 5;
    int lane = threadIdx.x & 31;
    if (warp >= NTOK) return;
    const float* xr = x + (size_t)warp * DDIM;

    float acc[NEXP];
#pragma unroll
    for (int e = 0; e < NEXP; e++) acc[e] = 0.f;
    for (int i = lane; i < DDIM; i += 32) {
        float xv = xr[i];
#pragma unroll
        for (int e = 0; e < NEXP; e++) acc[e] += xv * Wr[e * DDIM + i];
    }
#pragma unroll
    for (int e = 0; e < NEXP; e++) {
#pragma unroll
        for (int off = 16; off; off >>= 1)
            acc[e] += __shfl_xor_sync(0xffffffffu, acc[e], off);
    }
    if (lane == 0) {
        int i0 = 0;
#pragma unroll
        for (int e = 1; e < NEXP; e++)
            if (acc[e] > acc[i0]) i0 = e;
        int i1 = -1;
#pragma unroll
        for (int e = 0; e < NEXP; e++) {
            if (e == i0) continue;
            if (i1 < 0 || acc[e] > acc[i1]) i1 = e;
        }
        float ex  = expf(acc[i1] - acc[i0]);
        float inv = 1.f / (1.f + ex);
        int p0 = atomicAdd(&g_cnt[i0], 1);
        g_rows[i0][p0] = 2 * warp;
        int p1 = atomicAdd(&g_cnt[i1], 1);
        g_rows[i1][p1] = 2 * warp + 1;
        g_gate[2 * warp]     = inv;
        g_gate[2 * warp + 1] = ex * inv;
    }
}

// ---------------- grouped GEMM: fp16 m16n8k16, warp tile 64x64 -------------
// CTA 128x256; 8 warps 2(m) x 4(n). Fragment-major layout identical to R14.
template <int KTOT, int ROWSHIFT, int CSTRIDE, bool SQRELU, bool GATE>
__global__ __launch_bounds__(THREADS, 1)
void k_gemm(const float* __restrict__ Asrc, const float* __restrict__ Bsrc) {
    extern __shared__ char smem[];
    const int e   = blockIdx.z;
    const int cnt = g_cnt[e];
    const int m0  = blockIdx.y * BM;
    if (m0 >= cnt) return;
    const int n0  = blockIdx.x * BN;
    const int tid  = threadIdx.x;
    const int wid  = tid >> 5;
    const int lane = tid & 31;
    const int g    = lane >> 2;
    const int t    = lane & 3;
    const int wm   = wid >> 2;     // 0..1
    const int wn   = wid & 3;      // 0..3

    int*   s_a   = (int*)(smem + SM_META);
    int*   s_row = (int*)(smem + SM_META + 512);
    float* s_g   = (float*)(smem + SM_META + 1024);

    const float* Aptr = (ROWSHIFT == 1) ? Asrc : g_act;
    float*       Cptr = SQRELU ? g_act : g_y;

    if (tid < BM) {
        int idx = m0 + tid;
        int aid = g_rows[e][idx < cnt ? idx : cnt - 1];
        s_a[tid]   = aid;
        s_row[tid] = aid >> ROWSHIFT;
        if (GATE) s_g[tid] = g_gate[aid];
    }
    __syncthreads();

    const float* Bslab = Bsrc + (size_t)e * CSTRIDE * KTOT + (size_t)n0 * KTOT;

    // ---- staging precompute (32-bit gather offsets to save registers) ----
    // float4 chunk c4: row = c4>>3, kq = c4&7; ks = kq>>2, q2 = kq&3
    // A: 1024 chunks -> 4/thread ; B: 2048 chunks -> 8/thread
    uint32_t agoff[4]; uint32_t aoff[4];
    uint32_t bgoff[8]; uint32_t boff[8];
#pragma unroll
    for (int i = 0; i < 4; i++) {
        int c4  = tid + THREADS * i;
        int row = c4 >> 3, kq = c4 & 7;
        int ks = kq >> 2, q2 = kq & 3;
        int t0 = (2 * q2) & 3, hi = q2 >> 1;
        int MI = row >> 4, h = (row >> 3) & 1, gg = row & 7;
        aoff[i]  = (uint32_t)((MI * 2 + ks) * A_GRP_BYTES
                              + (4 * gg + t0) * 16 + h * 4 + hi * 8);
        agoff[i] = (uint32_t)(s_row[row] * KTOT + 4 * kq);
    }
#pragma unroll
    for (int i = 0; i < 8; i++) {
        int c4  = tid + THREADS * i;
        int row = c4 >> 3, kq = c4 & 7;
        int ks = kq >> 2, q2 = kq & 3;
        int t0 = (2 * q2) & 3, hi = q2 >> 1;
        int NI = row >> 3, gg = row & 7;
        boff[i]  = (uint32_t)((NI * 2 + ks) * B_GRP_BYTES
                              + (4 * gg + t0) * 8 + hi * 4);
        bgoff[i] = (uint32_t)(row * KTOT + 4 * kq);
    }

    float4 ra[4], rb[8];
    auto LDG = [&](int c) {
        const int k0 = c * BK;
#pragma unroll
        for (int i = 0; i < 4; i++) ra[i] = *(const float4*)(Aptr + agoff[i] + k0);
#pragma unroll
        for (int i = 0; i < 8; i++) rb[i] = *(const float4*)(Bslab + bgoff[i] + k0);
    };
    auto STS = [&](int s) {          // s = buffer parity
        char* stA = smem + s * STAGE_BYTES;
        char* stB = stA + A_BUF_BYTES;
#pragma unroll
        for (int i = 0; i < 4; i++) {
            *(uint32_t*)(stA + aoff[i])      = f2h2(ra[i].x, ra[i].y);
            *(uint32_t*)(stA + aoff[i] + 16) = f2h2(ra[i].z, ra[i].w);
        }
#pragma unroll
        for (int i = 0; i < 8; i++) {
            *(uint32_t*)(stB + boff[i])     = f2h2(rb[i].x, rb[i].y);
            *(uint32_t*)(stB + boff[i] + 8) = f2h2(rb[i].z, rb[i].w);
        }
    };

    float cacc[4][8][4];
#pragma unroll
    for (int mi = 0; mi < 4; mi++)
#pragma unroll
        for (int ni = 0; ni < 8; ni++)
#pragma unroll
            for (int r = 0; r < 4; r++) cacc[mi][ni][r] = 0.f;

    constexpr int NC = KTOT / BK;
    LDG(0);
    STS(0);
    __syncthreads();

    for (int c = 0; c < NC; c++) {
        if (c + 1 < NC) LDG(c + 1);      // prefetch next chunk into registers

        const char* Abuf = smem + (c & 1) * STAGE_BYTES;
        const char* Bbuf = Abuf + A_BUF_BYTES;
#pragma unroll
        for (int ks = 0; ks < 2; ks++) {
            uint4 af[4];
#pragma unroll
            for (int mi = 0; mi < 4; mi++) {
                int grp = (wm * 4 + mi) * 2 + ks;
                af[mi] = *(const uint4*)(Abuf + grp * A_GRP_BYTES + lane * 16);
            }
            // B in two halves of 4 frags to bound live registers
#pragma unroll
            for (int half = 0; half < 2; half++) {
                uint2 bf[4];
#pragma unroll
                for (int nj = 0; nj < 4; nj++) {
                    int ni = half * 4 + nj;
                    int grp = (wn * 8 + ni) * 2 + ks;
                    bf[nj] = *(const uint2*)(Bbuf + grp * B_GRP_BYTES + lane * 8);
                }
#pragma unroll
                for (int mi = 0; mi < 4; mi++)
#pragma unroll
                    for (int nj = 0; nj < 4; nj++)
                        mma_f16(cacc[mi][half * 4 + nj], &af[mi].x, &bf[nj].x);
            }
        }

        if (c + 1 < NC) STS((c + 1) & 1);   // other buffer; readers done at sync(c-1)
        __syncthreads();
    }

    // ---- epilogue: direct STG from accumulators ----
#pragma unroll
    for (int mi = 0; mi < 4; mi++) {
#pragma unroll
        for (int ni = 0; ni < 8; ni++) {
            const float* c = cacc[mi][ni];
            int rb_ = wm * 64 + mi * 16;
            int cb  = wn * 64 + ni * 8 + 2 * t;
#pragma unroll
            for (int h = 0; h < 2; h++) {
                int r = rb_ + g + h * 8;
                if (m0 + r < cnt) {
                    int aid = s_a[r];
                    float gv = GATE ? s_g[r] : 0.f;
#pragma unroll
                    for (int q = 0; q < 2; q++) {
                        float v = c[h * 2 + q];
                        if (SQRELU) v = (v > 0.f) ? v * v : 0.f;
                        if (GATE) v *= gv;
                        Cptr[(size_t)aid * CSTRIDE + n0 + cb + q] = v;
                    }
                }
            }
        }
    }
}

// ---------------- kernel 4: combine the two gated expert outputs -----------
__global__ void k_combine(float* __restrict__ out) {
    int i = blockIdx.x * blockDim.x + threadIdx.x;
    if (i >= NTOK * DDIM / 4) return;
    int n  = i / (DDIM / 4);
    int d4 = i % (DDIM / 4);
    const float4 a = *((const float4*)(g_y + (size_t)(2 * n) * DDIM) + d4);
    const float4 b = *((const float4*)(g_y + (size_t)(2 * n + 1) * DDIM) + d4);
    float4 o;
    o.x = a.x + b.x;
    o.y = a.y + b.y;
    o.z = a.z + b.z;
    o.w = a.w + b.w;
    *((float4*)(out + (size_t)n * DDIM) + d4) = o;
}

// ---------------- launch ----------------------------------------------------
extern "C" void kernel_launch(void* const* d_in, const int* in_sizes, int n_in,
                              void* d_out, int out_size) {
    const float* x  = (const float*)d_in[0];   // [2048, 1024]
    const float* Wr = (const float*)d_in[1];   // [8, 1024]
    const float* W1 = (const float*)d_in[2];   // [8, 2048, 1024]
    const float* W2 = (const float*)d_in[3];   // [8, 1024, 2048]
    float* out = (float*)d_out;                // [2048, 1024]
    (void)in_sizes; (void)n_in; (void)out_size;

    cudaFuncSetAttribute((const void*)k_gemm<DDIM, 1, FDIM, true, false>,
                         cudaFuncAttributeMaxDynamicSharedMemorySize, SM_TOTAL);
    cudaFuncSetAttribute((const void*)k_gemm<FDIM, 0, DDIM, false, true>,
                         cudaFuncAttributeMaxDynamicSharedMemorySize, SM_TOTAL);

    k_zero<<<1, 32>>>();
    k_router<<<NTOK / 8, 256>>>(x, Wr);

    // fc1: act[a, f] = relu(x[a>>1] . W1[e][f])^2
    k_gemm<DDIM, 1, FDIM, true, false>
        <<<dim3(FDIM / BN, NTOK / BM, NEXP), THREADS, SM_TOTAL>>>(x, W1);

    // fc2: y[a, d] = gate[a] * (act[a] . W2[e][d])
    k_gemm<FDIM, 0, DDIM, false, true>
        <<<dim3(DDIM / BN, NTOK / BM, NEXP), THREADS, SM_TOTAL>>>(nullptr, W2);

    k_combine<<<(NTOK * DDIM / 4 + 255) / 256, 256>>>(out);
}

// round 16
// speedup vs baseline: 1.2172x; 1.2172x over previous
#include <cuda_runtime.h>
#include <cuda_fp16.h>
#include <math.h>
#include <stdint.h>

#define NTOK 2048
#define DDIM 1024
#define NEXP 8
#define FDIM 2048
#define NASS (NTOK * 2)

// GEMM tiling: CTA 128x256, warp 64x32 (16 warps = 512 threads), BK=32
#define BM 128
#define BN 256
#define BK 32
#define THREADS 512

// fp16 fragment-major smem (double-buffered), m16n8k16 => 2 ks-slices per BK=32
//  A: 16 groups (MI 0..7 x ks 0..1), each 33 lines x 16B (line = lane's 4-reg frag)
//  B: 64 groups (NI 0..31 x ks 0..1), each 33 lines x 8B
#define A_GRP_BYTES (33 * 16)
#define B_GRP_BYTES (33 * 8)
#define A_BUF_BYTES (16 * A_GRP_BYTES)      // 8448
#define B_BUF_BYTES (64 * B_GRP_BYTES)      // 16896
#define STAGE_BYTES (A_BUF_BYTES + B_BUF_BYTES)   // 25344
#define SM_META     (2 * STAGE_BYTES)             // 50688
#define SM_TOTAL    (SM_META + 512 * 3)           // 52224

// ---------------- scratch (device globals) ---------------------------------
__device__ int    g_cnt[NEXP];
__device__ int    g_rows[NEXP][NTOK];
__device__ float  g_gate[NASS];
__device__ __half g_xh[(size_t)NTOK * DDIM];          // 4 MB
__device__ __half g_w1h[(size_t)NEXP * FDIM * DDIM];  // 32 MB
__device__ __half g_w2h[(size_t)NEXP * DDIM * FDIM];  // 32 MB
__device__ __half g_act[(size_t)NASS * FDIM];         // 16 MB (fp16 activations)
__device__ float  g_y[(size_t)NASS * DDIM];           // 16 MB

// ---------------- helpers ---------------------------------------------------
__device__ __forceinline__ void mma_f16(float* c, const unsigned* a, const unsigned* b) {
    asm volatile(
        "mma.sync.aligned.m16n8k16.row.col.f32.f16.f16.f32 "
        "{%0,%1,%2,%3}, {%4,%5,%6,%7}, {%8,%9}, {%0,%1,%2,%3};"
        : "+f"(c[0]), "+f"(c[1]), "+f"(c[2]), "+f"(c[3])
        : "r"(a[0]), "r"(a[1]), "r"(a[2]), "r"(a[3]), "r"(b[0]), "r"(b[1]));
}

// ---------------- kernel 0: zero expert counters ---------------------------
__global__ void k_zero() {
    if (threadIdx.x < NEXP) g_cnt[threadIdx.x] = 0;
}

// ---------------- fp32 -> fp16 streaming converter -------------------------
__global__ void k_cvt(const float4* __restrict__ src, uint2* __restrict__ dst, int n4) {
    int i = blockIdx.x * blockDim.x + threadIdx.x;
    if (i >= n4) return;
    float4 v = src[i];
    __half2 lo = __floats2half2_rn(v.x, v.y);
    __half2 hi = __floats2half2_rn(v.z, v.w);
    dst[i] = make_uint2(*(uint32_t*)&lo, *(uint32_t*)&hi);
}

// ---------------- kernel 1: router (one warp per token) --------------------
__global__ void k_router(const float* __restrict__ x, const float* __restrict__ Wr) {
    int warp = (blockIdx.x * blockDim.x + threadIdx.x) >> 5;
    int lane = threadIdx.x & 31;
    if (warp >= NTOK) return;
    const float* xr = x + (size_t)warp * DDIM;

    float acc[NEXP];
#pragma unroll
    for (int e = 0; e < NEXP; e++) acc[e] = 0.f;
    for (int i = lane; i < DDIM; i += 32) {
        float xv = xr[i];
#pragma unroll
        for (int e = 0; e < NEXP; e++) acc[e] += xv * Wr[e * DDIM + i];
    }
#pragma unroll
    for (int e = 0; e < NEXP; e++) {
#pragma unroll
        for (int off = 16; off; off >>= 1)
            acc[e] += __shfl_xor_sync(0xffffffffu, acc[e], off);
    }
    if (lane == 0) {
        int i0 = 0;
#pragma unroll
        for (int e = 1; e < NEXP; e++)
            if (acc[e] > acc[i0]) i0 = e;
        int i1 = -1;
#pragma unroll
        for (int e = 0; e < NEXP; e++) {
            if (e == i0) continue;
            if (i1 < 0 || acc[e] > acc[i1]) i1 = e;
        }
        float ex  = expf(acc[i1] - acc[i0]);
        float inv = 1.f / (1.f + ex);
        int p0 = atomicAdd(&g_cnt[i0], 1);
        g_rows[i0][p0] = 2 * warp;
        int p1 = atomicAdd(&g_cnt[i1], 1);
        g_rows[i1][p1] = 2 * warp + 1;
        g_gate[2 * warp]     = inv;
        g_gate[2 * warp + 1] = ex * inv;
    }
}

// ---------------- grouped GEMM: fp16 m16n8k16, fp16 gmem operands ----------
// CTA 128x256; 16 warps 2(m) x 4... (2m x 8n); warp 64x32. Double-buffered.
// Staging: A 1x LDG.128 (8 halves) -> 4x STS.32; B 2x LDG.128 -> 8x STS.32.
// Row-bit-permuted chunk maps make every STS.32 conflict-free (see derivation).
template <int KTOT, int ROWSHIFT, int CSTRIDE, bool SQRELU, bool GATE>
__global__ __launch_bounds__(THREADS, 1)
void k_gemm() {
    extern __shared__ char smem[];
    const int e   = blockIdx.z;
    const int cnt = g_cnt[e];
    const int m0  = blockIdx.y * BM;
    if (m0 >= cnt) return;
    const int n0  = blockIdx.x * BN;
    const int tid  = threadIdx.x;
    const int wid  = tid >> 5;
    const int lane = tid & 31;
    const int g    = lane >> 2;
    const int t    = lane & 3;
    const int wm   = wid >> 3;     // 0..1
    const int wn   = wid & 7;      // 0..7

    int*   s_a   = (int*)(smem + SM_META);
    int*   s_row = (int*)(smem + SM_META + 512);
    float* s_g   = (float*)(smem + SM_META + 1024);

    const __half* Aptr = (ROWSHIFT == 1) ? g_xh : g_act;
    const __half* Bptr = SQRELU ? g_w1h : g_w2h;

    if (tid < BM) {
        int idx = m0 + tid;
        int aid = g_rows[e][idx < cnt ? idx : cnt - 1];
        s_a[tid]   = aid;
        s_row[tid] = aid >> ROWSHIFT;
        if (GATE) s_g[tid] = g_gate[aid];
    }
    __syncthreads();

    const __half* Bslab = Bptr + (size_t)e * CSTRIDE * KTOT + (size_t)n0 * KTOT;

    // ---- staging precompute ----
    // A: 512 16B-chunks (row 0..127 x kc 0..3), 1/thread.
    //    Row-bit permutation q->row puts (gg&1, h, MI&1) in lane bits => STS
    //    banks 16(gg&1)+8(MI&1)+h+2hi+4ks+4p are all-distinct: conflict-free.
    uint32_t aoff, agoff;
    {
        int q = tid >> 2, kc = tid & 3;
        int row = (q & 1) | (((q >> 1) & 1) << 3) | (((q >> 2) & 1) << 4)
                | (((q >> 3) & 1) << 1) | (((q >> 4) & 1) << 2) | ((q >> 5) << 5);
        int ks = kc >> 1, hi = kc & 1;
        int MI = row >> 4, h = (row >> 3) & 1, gg = row & 7;
        aoff  = (uint32_t)((MI * 2 + ks) * A_GRP_BYTES + (4 * gg) * 16 + h * 4 + hi * 8);
        agoff = (uint32_t)(s_row[row] * KTOT + kc * 8);
    }
    // B: 1024 chunks (row 0..255 x kc 0..3), 2/thread. Permutation puts
    //    (gg&3, NI&1) in lane bits => banks 8(gg&3)+4(NI&1)+2ks+hi+2p distinct.
    uint32_t boff[2], bgoff[2];
#pragma unroll
    for (int i = 0; i < 2; i++) {
        int c = tid + THREADS * i;
        int q = c >> 2, kc = c & 3;
        int row = (q & 3) | (((q >> 2) & 1) << 3) | (((q >> 3) & 1) << 2) | ((q >> 4) << 4);
        int ks = kc >> 1, hi = kc & 1;
        int NI = row >> 3, gg = row & 7;
        boff[i]  = (uint32_t)((NI * 2 + ks) * B_GRP_BYTES + (4 * gg) * 8 + hi * 4);
        bgoff[i] = (uint32_t)(row * KTOT + kc * 8);
    }

    uint4 ha, hb[2];
    auto LDG = [&](int c) {
        const int k0 = c * BK;
        ha = *(const uint4*)(Aptr + agoff + k0);
#pragma unroll
        for (int i = 0; i < 2; i++) hb[i] = *(const uint4*)(Bslab + bgoff[i] + k0);
    };
    auto STS = [&](int s) {          // s = buffer parity
        char* stA = smem + s * STAGE_BYTES;
        char* stB = stA + A_BUF_BYTES;
        uint32_t av[4] = {ha.x, ha.y, ha.z, ha.w};
#pragma unroll
        for (int p = 0; p < 4; p++)
            *(uint32_t*)(stA + aoff + p * 16) = av[p];
#pragma unroll
        for (int i = 0; i < 2; i++) {
            uint32_t bv[4] = {hb[i].x, hb[i].y, hb[i].z, hb[i].w};
#pragma unroll
            for (int p = 0; p < 4; p++)
                *(uint32_t*)(stB + boff[i] + p * 8) = bv[p];
        }
    };

    float cacc[4][4][4];
#pragma unroll
    for (int mi = 0; mi < 4; mi++)
#pragma unroll
        for (int ni = 0; ni < 4; ni++)
#pragma unroll
            for (int r = 0; r < 4; r++) cacc[mi][ni][r] = 0.f;

    constexpr int NC = KTOT / BK;
    LDG(0);
    STS(0);
    __syncthreads();

    for (int c = 0; c < NC; c++) {
        if (c + 1 < NC) LDG(c + 1);      // prefetch next chunk into registers

        const char* Abuf = smem + (c & 1) * STAGE_BYTES;
        const char* Bbuf = Abuf + A_BUF_BYTES;
#pragma unroll
        for (int ks = 0; ks < 2; ks++) {
            uint4 af[4]; uint2 bf[4];
#pragma unroll
            for (int mi = 0; mi < 4; mi++) {
                int grp = (wm * 4 + mi) * 2 + ks;
                af[mi] = *(const uint4*)(Abuf + grp * A_GRP_BYTES + lane * 16);
            }
#pragma unroll
            for (int ni = 0; ni < 4; ni++) {
                int grp = (wn * 4 + ni) * 2 + ks;
                bf[ni] = *(const uint2*)(Bbuf + grp * B_GRP_BYTES + lane * 8);
            }
#pragma unroll
            for (int mi = 0; mi < 4; mi++)
#pragma unroll
                for (int ni = 0; ni < 4; ni++)
                    mma_f16(cacc[mi][ni], &af[mi].x, &bf[ni].x);
        }

        if (c + 1 < NC) STS((c + 1) & 1);   // other buffer; readers done at sync(c-1)
        __syncthreads();
    }

    // ---- epilogue ----
#pragma unroll
    for (int mi = 0; mi < 4; mi++) {
#pragma unroll
        for (int ni = 0; ni < 4; ni++) {
            const float* c = cacc[mi][ni];
            int rb_ = wm * 64 + mi * 16;
            int cb  = wn * 32 + ni * 8 + 2 * t;
#pragma unroll
            for (int h = 0; h < 2; h++) {
                int r = rb_ + g + h * 8;
                if (m0 + r < cnt) {
                    int aid = s_a[r];
                    if (SQRELU) {
                        float v0 = c[h * 2 + 0], v1 = c[h * 2 + 1];
                        v0 = (v0 > 0.f) ? v0 * v0 : 0.f;
                        v1 = (v1 > 0.f) ? v1 * v1 : 0.f;
                        __half2 h2 = __floats2half2_rn(v0, v1);
                        *(uint32_t*)(g_act + (size_t)aid * CSTRIDE + n0 + cb) =
                            *(uint32_t*)&h2;
                    } else {
                        float gv = s_g[r];
                        float* yrow = g_y + (size_t)aid * CSTRIDE + n0 + cb;
                        yrow[0] = c[h * 2 + 0] * gv;
                        yrow[1] = c[h * 2 + 1] * gv;
                    }
                }
            }
        }
    }
}

// ---------------- kernel 4: combine the two gated expert outputs -----------
__global__ void k_combine(float* __restrict__ out) {
    int i = blockIdx.x * blockDim.x + threadIdx.x;
    if (i >= NTOK * DDIM / 4) return;
    int n  = i / (DDIM / 4);
    int d4 = i % (DDIM / 4);
    const float4 a = *((const float4*)(g_y + (size_t)(2 * n) * DDIM) + d4);
    const float4 b = *((const float4*)(g_y + (size_t)(2 * n + 1) * DDIM) + d4);
    float4 o;
    o.x = a.x + b.x;
    o.y = a.y + b.y;
    o.z = a.z + b.z;
    o.w = a.w + b.w;
    *((float4*)(out + (size_t)n * DDIM) + d4) = o;
}

// ---------------- launch ----------------------------------------------------
extern "C" void kernel_launch(void* const* d_in, const int* in_sizes, int n_in,
                              void* d_out, int out_size) {
    const float* x  = (const float*)d_in[0];   // [2048, 1024]
    const float* Wr = (const float*)d_in[1];   // [8, 1024]
    const float* W1 = (const float*)d_in[2];   // [8, 2048, 1024]
    const float* W2 = (const float*)d_in[3];   // [8, 1024, 2048]
    float* out = (float*)d_out;                // [2048, 1024]
    (void)in_sizes; (void)n_in; (void)out_size;

    cudaFuncSetAttribute((const void*)k_gemm<DDIM, 1, FDIM, true, false>,
                         cudaFuncAttributeMaxDynamicSharedMemorySize, SM_TOTAL);
    cudaFuncSetAttribute((const void*)k_gemm<FDIM, 0, DDIM, false, true>,
                         cudaFuncAttributeMaxDynamicSharedMemorySize, SM_TOTAL);

    // fp16 scratch targets (device-symbol addresses via kernel-side globals)
    void *p_xh = nullptr, *p_w1 = nullptr, *p_w2 = nullptr;
    cudaGetSymbolAddress(&p_xh, g_xh);
    cudaGetSymbolAddress(&p_w1, g_w1h);
    cudaGetSymbolAddress(&p_w2, g_w2h);

    k_zero<<<1, 32>>>();

    const int n4x = NTOK * DDIM / 4;                    // 524288
    const int n4w = NEXP * FDIM * DDIM / 4;             // 4194304
    k_cvt<<<(n4x + 255) / 256, 256>>>((const float4*)x,  (uint2*)p_xh, n4x);
    k_cvt<<<(n4w + 255) / 256, 256>>>((const float4*)W1, (uint2*)p_w1, n4w);
    k_cvt<<<(n4w + 255) / 256, 256>>>((const float4*)W2, (uint2*)p_w2, n4w);

    k_router<<<NTOK / 8, 256>>>(x, Wr);

    // fc1: act[a, f] = fp16(relu(x[a>>1] . W1[e][f])^2)
    k_gemm<DDIM, 1, FDIM, true, false>
        <<<dim3(FDIM / BN, NTOK / BM, NEXP), THREADS, SM_TOTAL>>>();

    // fc2: y[a, d] = gate[a] * (act[a] . W2[e][d])
    k_gemm<FDIM, 0, DDIM, false, true>
        <<<dim3(DDIM / BN, NTOK / BM, NEXP), THREADS, SM_TOTAL>>>();

    k_combine<<<(NTOK * DDIM / 4 + 255) / 256, 256>>>(out);
}

// round 17
// speedup vs baseline: 1.2508x; 1.0276x over previous
#include <cuda_runtime.h>
#include <cuda_fp16.h>
#include <math.h>
#include <stdint.h>

#define NTOK 2048
#define DDIM 1024
#define NEXP 8
#define FDIM 2048
#define NASS (NTOK * 2)

// GEMM tiling: CTA 128x256, warp 64x32 (16 warps = 512 threads), BK=32
#define BM 128
#define BN 256
#define BK 32
#define THREADS 512
#define NSTAGE 4

// row-major swizzled tiles: row = 64B (32 halves), chunk kc 0..3 of 16B,
// smem addr = row*64 + ((kc ^ ((row>>1)&3)) << 4)   (conflict-free everywhere)
#define A_TILE_BYTES (BM * 64)              // 8192
#define B_TILE_BYTES (BN * 64)              // 16384
#define STAGE_BYTES  (A_TILE_BYTES + B_TILE_BYTES)   // 24576
#define SM_META      (NSTAGE * STAGE_BYTES)          // 98304
#define SM_TOTAL     (SM_META + 512 * 3)             // 99840

// ---------------- scratch (device globals) ---------------------------------
__device__ int    g_cnt[NEXP];
__device__ int    g_rows[NEXP][NTOK];
__device__ float  g_gate[NASS];
__device__ __half g_xh[(size_t)NTOK * DDIM];          // 4 MB
__device__ __half g_w1h[(size_t)NEXP * FDIM * DDIM];  // 32 MB
__device__ __half g_w2h[(size_t)NEXP * DDIM * FDIM];  // 32 MB
__device__ __half g_act[(size_t)NASS * FDIM];         // 16 MB
__device__ float  g_y[(size_t)NASS * DDIM];           // 16 MB

// ---------------- helpers ---------------------------------------------------
__device__ __forceinline__ void mma_f16(float* c, const unsigned* a, const unsigned* b) {
    asm volatile(
        "mma.sync.aligned.m16n8k16.row.col.f32.f16.f16.f32 "
        "{%0,%1,%2,%3}, {%4,%5,%6,%7}, {%8,%9}, {%0,%1,%2,%3};"
        : "+f"(c[0]), "+f"(c[1]), "+f"(c[2]), "+f"(c[3])
        : "r"(a[0]), "r"(a[1]), "r"(a[2]), "r"(a[3]), "r"(b[0]), "r"(b[1]));
}
__device__ __forceinline__ void ldsm_x4(uint32_t* d, uint32_t addr) {
    asm volatile("ldmatrix.sync.aligned.m8n8.x4.shared.b16 {%0,%1,%2,%3}, [%4];"
                 : "=r"(d[0]), "=r"(d[1]), "=r"(d[2]), "=r"(d[3]) : "r"(addr));
}
__device__ __forceinline__ void cp16(uint32_t dst, const void* src) {
    asm volatile("cp.async.ca.shared.global [%0], [%1], 16;" :: "r"(dst), "l"(src));
}
__device__ __forceinline__ void cp_commit() {
    asm volatile("cp.async.commit_group;" ::: "memory");
}
template <int Nn>
__device__ __forceinline__ void cp_wait() {
    asm volatile("cp.async.wait_group %0;" :: "n"(Nn) : "memory");
}
__device__ __forceinline__ uint32_t smem_u32(const void* p) {
    uint32_t a;
    asm("{ .reg .u64 t; cvta.to.shared.u64 t, %1; cvt.u32.u64 %0, t; }"
        : "=r"(a) : "l"(p));
    return a;
}

// ---------------- kernel 0: zero expert counters ---------------------------
__global__ void k_zero() {
    if (threadIdx.x < NEXP) g_cnt[threadIdx.x] = 0;
}

// ---------------- fp32 -> fp16 streaming converter (ILP 4) -----------------
__global__ void k_cvt(const float4* __restrict__ src, uint2* __restrict__ dst, int n4) {
    int i0 = (blockIdx.x * blockDim.x) * 4 + threadIdx.x;
#pragma unroll
    for (int j = 0; j < 4; j++) {
        int i = i0 + j * blockDim.x;
        if (i < n4) {
            float4 v = src[i];
            __half2 lo = __floats2half2_rn(v.x, v.y);
            __half2 hi = __floats2half2_rn(v.z, v.w);
            dst[i] = make_uint2(*(uint32_t*)&lo, *(uint32_t*)&hi);
        }
    }
}

// ---------------- kernel 1: router (one warp per token) --------------------
__global__ void k_router(const float* __restrict__ x, const float* __restrict__ Wr) {
    int warp = (blockIdx.x * blockDim.x + threadIdx.x) >> 5;
    int lane = threadIdx.x & 31;
    if (warp >= NTOK) return;
    const float* xr = x + (size_t)warp * DDIM;

    float acc[NEXP];
#pragma unroll
    for (int e = 0; e < NEXP; e++) acc[e] = 0.f;
    for (int i = lane; i < DDIM; i += 32) {
        float xv = xr[i];
#pragma unroll
        for (int e = 0; e < NEXP; e++) acc[e] += xv * Wr[e * DDIM + i];
    }
#pragma unroll
    for (int e = 0; e < NEXP; e++) {
#pragma unroll
        for (int off = 16; off; off >>= 1)
            acc[e] += __shfl_xor_sync(0xffffffffu, acc[e], off);
    }
    if (lane == 0) {
        int i0 = 0;
#pragma unroll
        for (int e = 1; e < NEXP; e++)
            if (acc[e] > acc[i0]) i0 = e;
        int i1 = -1;
#pragma unroll
        for (int e = 0; e < NEXP; e++) {
            if (e == i0) continue;
            if (i1 < 0 || acc[e] > acc[i1]) i1 = e;
        }
        float ex  = expf(acc[i1] - acc[i0]);
        float inv = 1.f / (1.f + ex);
        int p0 = atomicAdd(&g_cnt[i0], 1);
        g_rows[i0][p0] = 2 * warp;
        int p1 = atomicAdd(&g_cnt[i1], 1);
        g_rows[i1][p1] = 2 * warp + 1;
        g_gate[2 * warp]     = inv;
        g_gate[2 * warp + 1] = ex * inv;
    }
}

// ---------------- grouped GEMM: cp.async + ldmatrix + m16n8k16 -------------
// CTA 128x256; 16 warps 2(m) x 8(n); warp 64x32. 4-stage cp.async ring.
template <int KTOT, int ROWSHIFT, int CSTRIDE, bool SQRELU, bool GATE>
__global__ __launch_bounds__(THREADS, 1)
void k_gemm() {
    extern __shared__ char smem[];
    const int e   = blockIdx.z;
    const int cnt = g_cnt[e];
    const int m0  = blockIdx.y * BM;
    if (m0 >= cnt) return;
    const int n0  = blockIdx.x * BN;
    const int tid  = threadIdx.x;
    const int wid  = tid >> 5;
    const int lane = tid & 31;
    const int g    = lane >> 2;
    const int t    = lane & 3;
    const int wm   = wid >> 3;     // 0..1
    const int wn   = wid & 7;      // 0..7

    int*   s_a   = (int*)(smem + SM_META);
    int*   s_row = (int*)(smem + SM_META + 512);
    float* s_g   = (float*)(smem + SM_META + 1024);

    const __half* Aptr = (ROWSHIFT == 1) ? g_xh : g_act;
    const __half* Bptr = SQRELU ? g_w1h : g_w2h;

    if (tid < BM) {
        int idx = m0 + tid;
        int aid = g_rows[e][idx < cnt ? idx : cnt - 1];
        s_a[tid]   = aid;
        s_row[tid] = aid >> ROWSHIFT;
        if (GATE) s_g[tid] = g_gate[aid];
    }
    __syncthreads();

    const __half* Bslab = Bptr + (size_t)e * CSTRIDE * KTOT + (size_t)n0 * KTOT;
    const uint32_t sbase = smem_u32(smem);

    // ---- cp.async staging maps ----
    // A: 512 chunks: m = tid>>2 (0..127), kc = tid&3
    const int am  = tid >> 2, akc = tid & 3;
    const uint32_t a_dst = (uint32_t)(am * 64 + ((akc ^ ((am >> 1) & 3)) << 4));
    const __half*  a_src = Aptr + (size_t)s_row[am] * KTOT + akc * 8;
    // B: 1024 chunks: 2/thread
    uint32_t b_dst[2]; const __half* b_src[2];
#pragma unroll
    for (int i = 0; i < 2; i++) {
        int c = tid + THREADS * i;
        int bn = c >> 2, bkc = c & 3;
        b_dst[i] = (uint32_t)(bn * 64 + ((bkc ^ ((bn >> 1) & 3)) << 4));
        b_src[i] = Bslab + (size_t)bn * KTOT + bkc * 8;
    }

    auto ISSUE = [&](int s) {
        const int k0 = s * BK;
        const uint32_t st = sbase + (uint32_t)((s & (NSTAGE - 1)) * STAGE_BYTES);
        cp16(st + a_dst, a_src + k0);
#pragma unroll
        for (int i = 0; i < 2; i++)
            cp16(st + A_TILE_BYTES + b_dst[i], b_src[i] + k0);
        cp_commit();
    };

    // ---- ldmatrix lane addresses (ks=0; ks=1 = addr ^ 32) ----
    // A x4 for frag mi: matrices j: m = wm*64+mi*16+(j&1)*8+r, kc = (j>>1)
    uint32_t a_lm[4];
    {
        int j = lane >> 3, r = lane & 7;
#pragma unroll
        for (int mi = 0; mi < 4; mi++) {
            int m  = wm * 64 + mi * 16 + (j & 1) * 8 + r;
            int kc = j >> 1;
            a_lm[mi] = (uint32_t)(m * 64 + ((kc ^ ((m >> 1) & 3)) << 4));
        }
    }
    // B x4 pack p covers frags ni=2p,2p+1: n = wn*32+p*16+(j>>1)*8+r, kc = j&1
    uint32_t b_lm[2];
    {
        int j = lane >> 3, r = lane & 7;
#pragma unroll
        for (int p = 0; p < 2; p++) {
            int n  = wn * 32 + p * 16 + (j >> 1) * 8 + r;
            int kc = j & 1;
            b_lm[p] = (uint32_t)(n * 64 + ((kc ^ ((n >> 1) & 3)) << 4));
        }
    }

    float cacc[4][4][4];
#pragma unroll
    for (int mi = 0; mi < 4; mi++)
#pragma unroll
        for (int ni = 0; ni < 4; ni++)
#pragma unroll
            for (int r = 0; r < 4; r++) cacc[mi][ni][r] = 0.f;

    constexpr int NC = KTOT / BK;
    // prologue: 3 stages in flight
    ISSUE(0); ISSUE(1); ISSUE(2);

    for (int c = 0; c < NC; c++) {
        if (c + 3 < NC) ISSUE(c + 3);    // slot (c-1)&3: consumed + synced

        // wait stage c:  pending allowed = min(3, NC-1-c)
        {
            int rem = NC - 1 - c;
            if (rem >= 3)      cp_wait<3>();
            else if (rem == 2) cp_wait<2>();
            else if (rem == 1) cp_wait<1>();
            else               cp_wait<0>();
        }
        __syncthreads();

        const uint32_t stA = sbase + (uint32_t)((c & (NSTAGE - 1)) * STAGE_BYTES);
        const uint32_t stB = stA + A_TILE_BYTES;
#pragma unroll
        for (int ks = 0; ks < 2; ks++) {
            const uint32_t kx = ks ? 32u : 0u;
            uint32_t af[4][4], bf[2][4];
#pragma unroll
            for (int mi = 0; mi < 4; mi++) ldsm_x4(af[mi], stA + (a_lm[mi] ^ kx));
#pragma unroll
            for (int p = 0; p < 2; p++)    ldsm_x4(bf[p],  stB + (b_lm[p] ^ kx));
#pragma unroll
            for (int mi = 0; mi < 4; mi++) {
#pragma unroll
                for (int p = 0; p < 2; p++) {
                    mma_f16(cacc[mi][2 * p + 0], af[mi], &bf[p][0]);
                    mma_f16(cacc[mi][2 * p + 1], af[mi], &bf[p][2]);
                }
            }
        }

        if (c + 4 < NC) __syncthreads(); // readers done before slot c&3 reuse
    }

    // ---- epilogue ----
#pragma unroll
    for (int mi = 0; mi < 4; mi++) {
#pragma unroll
        for (int ni = 0; ni < 4; ni++) {
            const float* c = cacc[mi][ni];
            int rb_ = wm * 64 + mi * 16;
            int cb  = wn * 32 + ni * 8 + 2 * t;
#pragma unroll
            for (int h = 0; h < 2; h++) {
                int r = rb_ + g + h * 8;
                if (m0 + r < cnt) {
                    int aid = s_a[r];
                    if (SQRELU) {
                        float v0 = c[h * 2 + 0], v1 = c[h * 2 + 1];
                        v0 = (v0 > 0.f) ? v0 * v0 : 0.f;
                        v1 = (v1 > 0.f) ? v1 * v1 : 0.f;
                        __half2 h2 = __floats2half2_rn(v0, v1);
                        *(uint32_t*)(g_act + (size_t)aid * CSTRIDE + n0 + cb) =
                            *(uint32_t*)&h2;
                    } else {
                        float gv = s_g[r];
                        float* yrow = g_y + (size_t)aid * CSTRIDE + n0 + cb;
                        yrow[0] = c[h * 2 + 0] * gv;
                        yrow[1] = c[h * 2 + 1] * gv;
                    }
                }
            }
        }
    }
}

// ---------------- kernel 4: combine the two gated expert outputs -----------
__global__ void k_combine(float* __restrict__ out) {
    int i = blockIdx.x * blockDim.x + threadIdx.x;
    if (i >= NTOK * DDIM / 4) return;
    int n  = i / (DDIM / 4);
    int d4 = i % (DDIM / 4);
    const float4 a = *((const float4*)(g_y + (size_t)(2 * n) * DDIM) + d4);
    const float4 b = *((const float4*)(g_y + (size_t)(2 * n + 1) * DDIM) + d4);
    float4 o;
    o.x = a.x + b.x;
    o.y = a.y + b.y;
    o.z = a.z + b.z;
    o.w = a.w + b.w;
    *((float4*)(out + (size_t)n * DDIM) + d4) = o;
}

// ---------------- launch ----------------------------------------------------
extern "C" void kernel_launch(void* const* d_in, const int* in_sizes, int n_in,
                              void* d_out, int out_size) {
    const float* x  = (const float*)d_in[0];   // [2048, 1024]
    const float* Wr = (const float*)d_in[1];   // [8, 1024]
    const float* W1 = (const float*)d_in[2];   // [8, 2048, 1024]
    const float* W2 = (const float*)d_in[3];   // [8, 1024, 2048]
    float* out = (float*)d_out;                // [2048, 1024]
    (void)in_sizes; (void)n_in; (void)out_size;

    cudaFuncSetAttribute((const void*)k_gemm<DDIM, 1, FDIM, true, false>,
                         cudaFuncAttributeMaxDynamicSharedMemorySize, SM_TOTAL);
    cudaFuncSetAttribute((const void*)k_gemm<FDIM, 0, DDIM, false, true>,
                         cudaFuncAttributeMaxDynamicSharedMemorySize, SM_TOTAL);

    void *p_xh = nullptr, *p_w1 = nullptr, *p_w2 = nullptr;
    cudaGetSymbolAddress(&p_xh, g_xh);
    cudaGetSymbolAddress(&p_w1, g_w1h);
    cudaGetSymbolAddress(&p_w2, g_w2h);

    k_zero<<<1, 32>>>();

    const int n4x = NTOK * DDIM / 4;                    // 524288
    const int n4w = NEXP * FDIM * DDIM / 4;             // 4194304
    k_cvt<<<(n4x + 1023) / 1024, 256>>>((const float4*)x,  (uint2*)p_xh, n4x);
    k_cvt<<<(n4w + 1023) / 1024, 256>>>((const float4*)W1, (uint2*)p_w1, n4w);
    k_cvt<<<(n4w + 1023) / 1024, 256>>>((const float4*)W2, (uint2*)p_w2, n4w);

    k_router<<<NTOK / 8, 256>>>(x, Wr);

    // fc1: act[a, f] = fp16(relu(x[a>>1] . W1[e][f])^2)
    k_gemm<DDIM, 1, FDIM, true, false>
        <<<dim3(FDIM / BN, NTOK / BM, NEXP), THREADS, SM_TOTAL>>>();

    // fc2: y[a, d] = gate[a] * (act[a] . W2[e][d])
    k_gemm<FDIM, 0, DDIM, false, true>
        <<<dim3(DDIM / BN, NTOK / BM, NEXP), THREADS, SM_TOTAL>>>();

    k_combine<<<(NTOK * DDIM / 4 + 255) / 256, 256>>>(out);
}